// round 13
// baseline (speedup 1.0000x reference)
#include <cuda_runtime.h>
#include <cuda_bf16.h>

#define BATCH  4
#define NB     2048
#define NC     4
#define ROWSL  16          // u16 slots per row: [0]=count, [1..15]=neighbors
#define MAXDEG 15
#define NBINS  64
#define GRID_F 128         // < 148 SMs @ 1 block/SM -> all co-resident (no deadlock)
#define TPB_F  512

// __device__ scratch (allocation-free rule). uint4 => 32B-aligned rows.
__device__ uint4 g_adj_raw[(size_t)BATCH * NB * ROWSL / 8];
#define G_ADJ ((unsigned short*)g_adj_raw)
__device__ float4         g_sbox[BATCH * NB];      // bin-sorted boxes (by x1)
__device__ unsigned short g_sidx[BATCH * NB];      // sorted pos -> original idx
__device__ int            g_binoff[BATCH][NBINS + 1];
__device__ float          g_meta[BATCH][4];        // minx, scale, wmax, binw
__device__ float          g_sink[GRID_F];          // prefetch DCE guard

// Grid barrier state (replay-safe: gen is monotone, cnt returns to 0).
__device__ unsigned           g_barcnt = 0;
__device__ volatile unsigned  g_bargen = 0;

__device__ __forceinline__ void gridbar() {
    __syncthreads();
    if (threadIdx.x == 0) {
        unsigned gen = g_bargen;
        __threadfence();
        unsigned t = atomicAdd(&g_barcnt, 1);
        if (t == GRID_F - 1) {
            atomicExch(&g_barcnt, 0);
            __threadfence();
            g_bargen = gen + 1;
        } else {
            while (g_bargen == gen) { }
            __threadfence();
        }
    }
    __syncthreads();
}

__device__ __forceinline__ unsigned flipkey(float s) {
    unsigned u = __float_as_uint(s);
    return (u & 0x80000000u) ? ~u : (u | 0x80000000u);   // total order on floats
}

// ---------------------------------------------------------------------------
// Dynamic smem union offsets (bytes). Total FS_SMEM.
// Phase A (sort):  wh@0 4KB, wcur@4096 4KB, hist64@8192, boff@8448,
//                  red@8708.., meta@8912
// Phase B (adj):   sx1@0 sy1@8192 sx2@16384 sy2@24576 sar@32768 (40KB),
//                  ssidx@40960 4KB, sboff@45056, rowbox@45328, lohit@45584
// Phase C (mis):   skey@0 8KB | fb: fsbox@0 32KB fsar@32768 8KB;
//                  sst@43008 2KB, scnt@45056
// ---------------------------------------------------------------------------
#define FS_SMEM 45600

__global__ void __launch_bounds__(TPB_F) fused_kernel(const float4* __restrict__ boxes,
                                                      const float* __restrict__ scores,
                                                      const float* __restrict__ thrp,
                                                      const float* __restrict__ sthrp,
                                                      float* __restrict__ out) {
    extern __shared__ unsigned char sm[];
    int tid = threadIdx.x, lane = tid & 31, warp = tid >> 5;
    int blk = blockIdx.x;
    float thr  = thrp[0];
    float sthr = sthrp[0];

    // =====================  PHASE A: sort (blocks 0..3)  =====================
    if (blk < BATCH) {
        int*   wh     = (int*)(sm + 0);        // [16][64] per-warp hist
        int*   wcur   = (int*)(sm + 4096);     // [16][64] cursors
        int*   hist64 = (int*)(sm + 8192);
        int*   boff   = (int*)(sm + 8448);     // 65 ints
        float* rmin   = (float*)(sm + 8708);
        float* rmax   = (float*)(sm + 8772);
        float* rw     = (float*)(sm + 8836);
        float* smeta  = (float*)(sm + 8912);   // minx, scale

        int b = blk;
        for (int i = tid; i < 16 * 64; i += TPB_F) wh[i] = 0;

        const float4* bb = boxes + (size_t)b * NB;
        float4 v[4];
        #pragma unroll
        for (int j = 0; j < 4; j++) v[j] = bb[tid + j * TPB_F];

        float mn = 1e30f, mx = -1e30f, w = -1e30f;
        #pragma unroll
        for (int j = 0; j < 4; j++) {
            mn = fminf(mn, v[j].x);
            mx = fmaxf(mx, v[j].x);
            w  = fmaxf(w, v[j].z - v[j].x);
        }
        #pragma unroll
        for (int o = 16; o; o >>= 1) {
            mn = fminf(mn, __shfl_xor_sync(0xffffffffu, mn, o));
            mx = fmaxf(mx, __shfl_xor_sync(0xffffffffu, mx, o));
            w  = fmaxf(w,  __shfl_xor_sync(0xffffffffu, w,  o));
        }
        if (lane == 0) { rmin[warp] = mn; rmax[warp] = mx; rw[warp] = w; }
        __syncthreads();
        if (warp == 0) {
            mn = (lane < 16) ? rmin[lane] : 1e30f;
            mx = (lane < 16) ? rmax[lane] : -1e30f;
            w  = (lane < 16) ? rw[lane] : -1e30f;
            #pragma unroll
            for (int o = 16; o; o >>= 1) {
                mn = fminf(mn, __shfl_xor_sync(0xffffffffu, mn, o));
                mx = fmaxf(mx, __shfl_xor_sync(0xffffffffu, mx, o));
                w  = fmaxf(w,  __shfl_xor_sync(0xffffffffu, w,  o));
            }
            if (lane == 0) {
                float span = fmaxf(mx - mn, 1e-20f);
                smeta[0] = mn;
                smeta[1] = (float)NBINS / span;
                g_meta[b][0] = mn;
                g_meta[b][1] = smeta[1];
                g_meta[b][2] = fmaxf(w, 0.0f);
                g_meta[b][3] = span / (float)NBINS;
            }
        }
        __syncthreads();

        float minx = smeta[0], scale = smeta[1];
        int bin[4];
        #pragma unroll
        for (int j = 0; j < 4; j++) {
            bin[j] = min(NBINS - 1, max(0, (int)((v[j].x - minx) * scale)));
            atomicAdd(&wh[warp * 64 + bin[j]], 1);
        }
        __syncthreads();

        if (tid < 64) {
            int acc = 0;
            #pragma unroll
            for (int wdx = 0; wdx < 16; wdx++) {
                int t = wh[wdx * 64 + tid];
                wcur[wdx * 64 + tid] = acc;
                acc += t;
            }
            hist64[tid] = acc;
        }
        __syncthreads();

        if (warp == 0) {
            int a0 = hist64[lane], a1 = hist64[lane + 32];
            #pragma unroll
            for (int o = 1; o < 32; o <<= 1) {
                int n = __shfl_up_sync(0xffffffffu, a0, o);
                if (lane >= o) a0 += n;
            }
            int tot0 = __shfl_sync(0xffffffffu, a0, 31);
            #pragma unroll
            for (int o = 1; o < 32; o <<= 1) {
                int n = __shfl_up_sync(0xffffffffu, a1, o);
                if (lane >= o) a1 += n;
            }
            a1 += tot0;
            if (lane == 0) { boff[0] = 0; g_binoff[b][0] = 0; }
            boff[lane + 1] = a0;   g_binoff[b][lane + 1] = a0;
            boff[lane + 33] = a1;  g_binoff[b][lane + 33] = a1;
        }
        __syncthreads();

        for (int i = tid; i < 16 * 64; i += TPB_F) wcur[i] += boff[i & 63];
        __syncthreads();

        #pragma unroll
        for (int j = 0; j < 4; j++) {
            int p = atomicAdd(&wcur[warp * 64 + bin[j]], 1);
            g_sbox[b * NB + p] = v[j];
            g_sidx[b * NB + p] = (unsigned short)(tid + j * TPB_F);
        }
    } else {
        // L2 prefetch of scores for phase C (blocks 4..127).
        float acc = 0.0f;
        int total = BATCH * NC * NB;
        for (int i = (blk - BATCH) * TPB_F + tid; i < total; i += (GRID_F - BATCH) * TPB_F)
            acc += scores[i];
        g_sink[blk] = acc;       // DCE guard; deterministic scratch write
    }

    gridbar();

    // ==================  PHASE B: adjacency (all blocks, 4 tiles)  ==================
    {
        float* sx1 = (float*)(sm + 0);
        float* sy1 = (float*)(sm + 8192);
        float* sx2 = (float*)(sm + 16384);
        float* sy2 = (float*)(sm + 24576);
        float* sar = (float*)(sm + 32768);
        unsigned short* ssidx = (unsigned short*)(sm + 40960);
        int*    sboff  = (int*)(sm + 45056);
        float4* rowbox = (float4*)(sm + 45328);
        int*    slh    = (int*)(sm + 45584);

        int b = (blk * 4) >> 7;                 // constant within block (128 % 4 == 0)
        float minx = g_meta[b][0], scale = g_meta[b][1];
        float wmax = g_meta[b][2], binw = g_meta[b][3];
        bool windowed = (thr >= 0.0f);

        if (tid <= NBINS) sboff[tid] = g_binoff[b][tid];
        const float4* sb = g_sbox + (size_t)b * NB;

        for (int tt = 0; tt < 4; tt++) {
            int tile   = blk * 4 + tt;
            int tilein = tile & 127;

            if (tid < 16) rowbox[tid] = sb[tilein * 16 + tid];
            __syncthreads();

            if (warp == 0) {
                float4 rv = rowbox[lane & 15];
                float r1 = rv.x, r2 = rv.z;
                #pragma unroll
                for (int o = 16; o; o >>= 1) {
                    r1 = fminf(r1, __shfl_xor_sync(0xffffffffu, r1, o));
                    r2 = fmaxf(r2, __shfl_xor_sync(0xffffffffu, r2, o));
                }
                if (lane == 0) {
                    int lo = 0, hi = NB;
                    if (windowed) {
                        int bl = min(NBINS - 1, max(0, (int)((r1 - wmax - minx) * scale) - 1));
                        int bh = min(NBINS, max(1, (int)((r2 - minx) * scale) + 2));
                        lo = sboff[bl] & ~31;
                        hi = min(NB, (sboff[bh] + 31) & ~31);
                    }
                    slh[0] = lo; slh[1] = hi;
                }
            }
            __syncthreads();
            int lo = slh[0], hi = slh[1];

            for (int i = lo + tid; i < hi; i += TPB_F) {
                float4 v = sb[i];
                int k = i - lo;
                sx1[k] = v.x; sy1[k] = v.y; sx2[k] = v.z; sy2[k] = v.w;
                sar[k] = (v.z - v.x) * (v.w - v.y);
                ssidx[k] = g_sidx[b * NB + i];
            }
            __syncthreads();

            int p = tilein * 16 + warp;
            float4 rv = rowbox[warp];
            float rx1 = rv.x, ry1 = rv.y, rx2 = rv.z, ry2 = rv.w;
            float rar = (rx2 - rx1) * (ry2 - ry1);
            int orr = ssidx[p - lo];
            unsigned short* row = G_ADJ + (size_t)(b * NB + orr) * ROWSL;
            int cnt = 0;

            int c0 = lo >> 5;
            if (windowed) {
                int bl = min(NBINS - 1, max(0, (int)((rx1 - wmax - minx) * scale) - 1));
                c0 = max(c0, sboff[bl] >> 5);
            }

            for (int c = c0; c < (hi >> 5); c++) {
                if (windowed) {
                    // bin-safe break: remaining elems have x1 >= binlo(bc)-slack
                    float x1c = sx1[c * 32 - lo];
                    int bc2 = min(NBINS - 1, max(0, (int)((x1c - minx) * scale)));
                    if (minx + (float)(bc2 - 1) * binw > rx2) break;
                }
                int k = c * 32 + lane - lo;
                float ix = fminf(rx2, sx2[k]) - fmaxf(rx1, sx1[k]);
                float iy = fminf(ry2, sy2[k]) - fmaxf(ry1, sy1[k]);
                ix = fmaxf(ix, 0.0f);
                iy = fmaxf(iy, 0.0f);
                float inter = ix * iy;
                float unim  = fmaxf(rar + sar[k] - inter, 1e-6f);
                bool hit = (inter > thr * unim) && (c * 32 + lane != p);
                unsigned word = __ballot_sync(0xffffffffu, hit);
                if (lane == 0 && word) {
                    int base = c * 32 - lo;
                    while (word) {
                        int j = __ffs(word) - 1;
                        word &= word - 1u;
                        if (cnt < MAXDEG) row[1 + cnt] = ssidx[base + j];
                        cnt++;                       // exact count even if truncated
                    }
                }
            }
            if (lane == 0) row[0] = (unsigned short)cnt;
            __syncthreads();                         // smem reuse across tiles
        }
    }

    gridbar();

    // ==================  PHASE C: MIS greedy (blocks 0..15)  ==================
    if (blk < BATCH * NC) {
        unsigned*               skey  = (unsigned*)(sm + 0);
        float4*                 fsbox = (float4*)(sm + 0);
        float*                  fsar  = (float*)(sm + 32768);
        volatile unsigned char* sst   = sm + 43008;
        volatile int*           scnt  = (int*)(sm + 45056);

        int bc = blk, b = bc >> 2;
        bool selfm = thr < 1.0f;
        const float* spc = scores + (size_t)bc * NB;
        float*       opc = out + (size_t)bc * NB;

        if (tid == 0) scnt[1] = 0;

        int nn[4];
        ushort4 rbuf[4][4];
        int dd[4];
        unsigned char stt[4];
        #pragma unroll
        for (int k = 0; k < 4; k++) {
            nn[k] = tid + k * TPB_F;
            const uint4* g0 = (const uint4*)(G_ADJ + (size_t)(b * NB + nn[k]) * ROWSL);
            uint4 a = g0[0], a2 = g0[1];
            rbuf[k][0] = *(ushort4*)&a.x;  rbuf[k][1] = *(ushort4*)&a.z;
            rbuf[k][2] = *(ushort4*)&a2.x; rbuf[k][3] = *(ushort4*)&a2.z;
        }
        #pragma unroll
        for (int k = 0; k < 4; k++) {
            const unsigned short* e = (const unsigned short*)rbuf[k];
            dd[k] = e[0];
            if (dd[k] > MAXDEG) scnt[1] = 1;
            float s = spc[nn[k]];
            skey[nn[k]] = flipkey(s);
            if (s > sthr) {
                if (dd[k] == 0) { stt[k] = 3; opc[nn[k]] = selfm ? (float)nn[k] : -1.0f; }
                else stt[k] = 0;
            } else { stt[k] = 3; opc[nn[k]] = -1.0f; }
            sst[nn[k]] = stt[k];
        }
        __syncthreads();

        if (scnt[1] == 0) {
            bool uu[4];
            #pragma unroll
            for (int k = 0; k < 4; k++) uu[k] = (stt[k] == 0);

            for (int round = 0; round < 4096; round++) {
                bool any = false;
                #pragma unroll
                for (int k = 0; k < 4; k++) {
                    if (!uu[k]) continue;
                    const unsigned short* e = (const unsigned short*)rbuf[k];
                    unsigned mk = skey[nn[k]];
                    bool blocked = false, claimed = false;
                    #pragma unroll
                    for (int q = 1; q <= MAXDEG; q++) {
                        if (q > dd[k]) break;
                        int u = e[q];
                        unsigned char stu = sst[u];
                        if (stu >= 2) continue;
                        unsigned fu = skey[u];
                        bool hp = (fu > mk) || (fu == mk && u < nn[k]);
                        if (!hp) continue;
                        if (stu == 1) { claimed = true; break; }
                        blocked = true;
                    }
                    if (claimed)       { sst[nn[k]] = 2; uu[k] = false; }
                    else if (!blocked) { sst[nn[k]] = 1; uu[k] = false; }
                    else any = true;
                }
                if (any) scnt[0] = round + 1;        // benign race: same value
                __syncthreads();
                if (scnt[0] != round + 1) break;
            }

            #pragma unroll
            for (int k = 0; k < 4; k++) {
                unsigned char f = sst[nn[k]];
                if (f == 1) opc[nn[k]] = (float)nn[k];
                else if (f == 2) {
                    const unsigned short* e = (const unsigned short*)rbuf[k];
                    unsigned bk = 0; int bu = -1;
                    #pragma unroll
                    for (int q = 1; q <= MAXDEG; q++) {
                        if (q > dd[k]) break;
                        int u = e[q];
                        if (sst[u] == 1) {
                            unsigned fu = skey[u];
                            if (bu < 0 || fu > bk || (fu == bk && u < bu)) { bk = fu; bu = u; }
                        }
                    }
                    opc[nn[k]] = (float)bu;
                }
            }
        } else {
            // ---- exact serial fallback for THIS (b,c) (adversarial only) ----
            const float4* bb = boxes + (size_t)b * NB;
            for (int i = tid; i < NB; i += TPB_F) {
                float4 v = bb[i];
                fsbox[i] = v;
                fsar[i] = (v.z - v.x) * (v.w - v.y);
            }
            for (int n = tid; n < NB; n += TPB_F) {
                sst[n] = (spc[n] > sthr) ? 0 : 1;
                opc[n] = -1.0f;
            }
            __syncthreads();

            if (warp == 0) {
                for (;;) {
                    float bs = -1e30f; int bi = 1 << 30;
                    for (int k = 0; k < NB / 32; k++) {
                        int u = k * 32 + lane;
                        if (!sst[u]) {
                            float s = spc[u];
                            if (s > bs || (s == bs && u < bi)) { bs = s; bi = u; }
                        }
                    }
                    #pragma unroll
                    for (int off = 16; off; off >>= 1) {
                        float os = __shfl_down_sync(0xffffffffu, bs, off);
                        int   oi = __shfl_down_sync(0xffffffffu, bi, off);
                        if (os > bs || (os == bs && oi < bi)) { bs = os; bi = oi; }
                    }
                    bi = __shfl_sync(0xffffffffu, bi, 0);
                    if (bi >= (1 << 30)) break;

                    float4 tb = fsbox[bi];
                    float tar = fsar[bi];
                    float lf = (float)bi;
                    for (int k = 0; k < NB / 32; k++) {
                        int u = k * 32 + lane;
                        if (!sst[u]) {
                            float4 ub = fsbox[u];
                            float ix = fminf(tb.z, ub.z) - fmaxf(tb.x, ub.x);
                            float iy = fminf(tb.w, ub.w) - fmaxf(tb.y, ub.y);
                            ix = fmaxf(ix, 0.0f);
                            iy = fmaxf(iy, 0.0f);
                            float inter = ix * iy;
                            float unim  = fmaxf(tar + fsar[u] - inter, 1e-6f);
                            if (inter > thr * unim) { sst[u] = 1; opc[u] = lf; }
                        }
                    }
                    if (lane == 0) sst[bi] = 1;
                    __syncwarp();
                }
            }
        }
    }
}

// ---------------------------------------------------------------------------
extern "C" void kernel_launch(void* const* d_in, const int* in_sizes, int n_in,
                              void* d_out, int out_size) {
    const float4* boxes  = (const float4*)d_in[0];
    const float*  scores = (const float*)d_in[1];
    const float*  iouthr = (const float*)d_in[2];
    const float*  scothr = (const float*)d_in[3];
    float* out = (float*)d_out;

    cudaFuncSetAttribute(fused_kernel,
                         cudaFuncAttributeMaxDynamicSharedMemorySize, FS_SMEM);

    fused_kernel<<<GRID_F, TPB_F, FS_SMEM>>>(boxes, scores, iouthr, scothr, out);
}

// round 14
// speedup vs baseline: 1.2279x; 1.2279x over previous
#include <cuda_runtime.h>
#include <cuda_bf16.h>

#define BATCH  4
#define NB     2048
#define NC     4
#define ROWSL  16          // u16 slots per row: [0]=count, [1..15]=neighbors
#define MAXDEG 15
#define NBINS  64
#define XSCALE 0.0625f     // fixed binning: bin = clamp((int)(x1/16), 0, 63)
#define BINW   16.0f

// __device__ scratch (allocation-free rule). uint4 => 32B-aligned rows.
__device__ uint4 g_adj_raw[(size_t)BATCH * NB * ROWSL / 8];
#define G_ADJ ((unsigned short*)g_adj_raw)
__device__ float4         g_sbox[BATCH * NB];      // bin-sorted boxes (by x1)
__device__ unsigned short g_sidx[BATCH * NB];      // sorted pos -> original idx
__device__ int            g_binoff[BATCH][NBINS + 1];
__device__ float          g_wmax[BATCH];           // per-batch max box width

// ---------------------------------------------------------------------------
// K0: per-batch counting sort into FIXED x1 bins. grid = BATCH, 1024 thr.
// No range reduction on the critical path; wmax reduced by a side warp.
// ---------------------------------------------------------------------------
__global__ void __launch_bounds__(1024) sort_kernel(const float4* __restrict__ boxes) {
    __shared__ int   wh[32 * 64];     // per-warp hist
    __shared__ int   wcur[32 * 64];   // absolute scatter cursors
    __shared__ int   hist64[64];
    __shared__ int   boff[NBINS + 1];
    __shared__ float rw[32];

    int b = blockIdx.x, tid = threadIdx.x;
    int lane = tid & 31, warp = tid >> 5;

    wh[tid] = 0; wh[tid + 1024] = 0;

    const float4* bb = boxes + (size_t)b * NB;
    float4 v0 = bb[tid], v1 = bb[tid + 1024];

    // side reduction: max width (consumed by adj, not by this kernel)
    float w = fmaxf(v0.z - v0.x, v1.z - v1.x);
    #pragma unroll
    for (int o = 16; o; o >>= 1)
        w = fmaxf(w, __shfl_xor_sync(0xffffffffu, w, o));
    if (lane == 0) rw[warp] = w;

    int bin0 = min(NBINS - 1, max(0, (int)(v0.x * XSCALE)));
    int bin1 = min(NBINS - 1, max(0, (int)(v1.x * XSCALE)));
    __syncthreads();                               // wh zeroed

    atomicAdd(&wh[warp * 64 + bin0], 1);           // intra-warp contention only
    atomicAdd(&wh[warp * 64 + bin1], 1);
    __syncthreads();

    // Column scan (64 threads) + wmax reduce (warp 2) in parallel.
    if (tid < 64) {
        int acc = 0;
        #pragma unroll 8
        for (int wdx = 0; wdx < 32; wdx++) {
            int t = wh[wdx * 64 + tid];
            wcur[wdx * 64 + tid] = acc;
            acc += t;
        }
        hist64[tid] = acc;
    } else if (warp == 2) {
        float m = rw[lane];
        #pragma unroll
        for (int o = 16; o; o >>= 1)
            m = fmaxf(m, __shfl_xor_sync(0xffffffffu, m, o));
        if (lane == 0) g_wmax[b] = fmaxf(m, 0.0f);
    }
    __syncthreads();

    // Warp-scan prefix over 64 bin totals.
    if (warp == 0) {
        int a0 = hist64[lane], a1 = hist64[lane + 32];
        #pragma unroll
        for (int o = 1; o < 32; o <<= 1) {
            int n = __shfl_up_sync(0xffffffffu, a0, o);
            if (lane >= o) a0 += n;
        }
        int tot0 = __shfl_sync(0xffffffffu, a0, 31);
        #pragma unroll
        for (int o = 1; o < 32; o <<= 1) {
            int n = __shfl_up_sync(0xffffffffu, a1, o);
            if (lane >= o) a1 += n;
        }
        a1 += tot0;
        if (lane == 0) { boff[0] = 0; g_binoff[b][0] = 0; }
        boff[lane + 1] = a0;   g_binoff[b][lane + 1] = a0;
        boff[lane + 33] = a1;  g_binoff[b][lane + 33] = a1;
    }
    __syncthreads();

    wcur[tid]        += boff[tid & 63];
    wcur[tid + 1024] += boff[tid & 63];
    __syncthreads();

    int p0 = atomicAdd(&wcur[warp * 64 + bin0], 1);
    g_sbox[b * NB + p0] = v0;
    g_sidx[b * NB + p0] = (unsigned short)tid;
    int p1 = atomicAdd(&wcur[warp * 64 + bin1], 1);
    g_sbox[b * NB + p1] = v1;
    g_sidx[b * NB + p1] = (unsigned short)(tid + 1024);
}

// ---------------------------------------------------------------------------
// K1: adjacency rows over bin-sorted boxes. 512 blocks x 512 thr, 16 rows.
// Fixed binning: minx=0, scale/binw compile-time. Bin-safe break (within a
// bin x1 is unordered; (bc-1)*BINW is a true lower bound for bins >= bc,
// and bin 0 — the only clamp-from-below bin — is never skipped by break).
// Rows written at ORIGINAL indices.
// ---------------------------------------------------------------------------
__global__ void __launch_bounds__(512) adj_kernel(const float* __restrict__ thrp) {
    __shared__ float sx1[NB], sy1[NB], sx2[NB], sy2[NB], sar[NB];
    __shared__ unsigned short ssidx[NB];
    __shared__ int sboff[NBINS + 1];
    __shared__ float4 rowbox[16];
    __shared__ int s_lo, s_hi;

    int b    = blockIdx.x >> 7;
    int tile = blockIdx.x & 127;
    int tid  = threadIdx.x;
    int warp = tid >> 5, lane = tid & 31;

    float thr  = thrp[0];
    float wmax = g_wmax[b];
    bool windowed = (thr >= 0.0f);       // hit => x-overlap only valid for thr>=0

    if (tid <= NBINS) sboff[tid] = g_binoff[b][tid];
    if (tid < 16) rowbox[tid] = g_sbox[b * NB + tile * 16 + tid];
    __syncthreads();

    // Window for this block's 16 rows.
    if (warp == 0) {
        float4 rv = rowbox[lane & 15];
        float r1 = rv.x, r2 = rv.z;
        #pragma unroll
        for (int o = 16; o; o >>= 1) {
            r1 = fminf(r1, __shfl_xor_sync(0xffffffffu, r1, o));
            r2 = fmaxf(r2, __shfl_xor_sync(0xffffffffu, r2, o));
        }
        if (lane == 0) {
            int lo = 0, hi = NB;
            if (windowed) {
                int bl = min(NBINS - 1, max(0, (int)((r1 - wmax) * XSCALE) - 1));
                int bh = min(NBINS, max(1, (int)(r2 * XSCALE) + 2));
                lo = sboff[bl] & ~31;
                hi = min(NB, (sboff[bh] + 31) & ~31);
            }
            s_lo = lo; s_hi = hi;
        }
    }
    __syncthreads();
    int lo = s_lo, hi = s_hi;

    // Stage the window.
    const float4* sb = g_sbox + (size_t)b * NB;
    for (int i = lo + tid; i < hi; i += 512) {
        float4 v = sb[i];
        int k = i - lo;
        sx1[k] = v.x; sy1[k] = v.y; sx2[k] = v.z; sy2[k] = v.w;
        sar[k] = (v.z - v.x) * (v.w - v.y);
        ssidx[k] = g_sidx[b * NB + i];
    }
    __syncthreads();

    int p = tile * 16 + warp;            // sorted position of this row
    float4 rv = rowbox[warp];
    float rx1 = rv.x, ry1 = rv.y, rx2 = rv.z, ry2 = rv.w;
    float rar = (rx2 - rx1) * (ry2 - ry1);
    int orr = ssidx[p - lo];
    unsigned short* row = G_ADJ + (size_t)(b * NB + orr) * ROWSL;
    int cnt = 0;

    int c0 = lo >> 5;
    if (windowed) {
        int bl = min(NBINS - 1, max(0, (int)((rx1 - wmax) * XSCALE) - 1));
        c0 = max(c0, sboff[bl] >> 5);
    }

    for (int c = c0; c < (hi >> 5); c++) {
        if (windowed) {
            float x1c = sx1[c * 32 - lo];
            int bc = min(NBINS - 1, max(0, (int)(x1c * XSCALE)));
            if ((float)(bc - 1) * BINW > rx2) break;   // bin-safe lower bound
        }
        int k = c * 32 + lane - lo;
        float ix = fminf(rx2, sx2[k]) - fmaxf(rx1, sx1[k]);
        float iy = fminf(ry2, sy2[k]) - fmaxf(ry1, sy1[k]);
        ix = fmaxf(ix, 0.0f);
        iy = fmaxf(iy, 0.0f);
        float inter = ix * iy;
        float unim  = fmaxf(rar + sar[k] - inter, 1e-6f);
        bool hit = (inter > thr * unim) && (c * 32 + lane != p);   // drop self
        unsigned word = __ballot_sync(0xffffffffu, hit);
        if (lane == 0 && word) {
            int base = c * 32 - lo;
            while (word) {
                int j = __ffs(word) - 1;
                word &= word - 1u;
                if (cnt < MAXDEG) row[1 + cnt] = ssidx[base + j];
                cnt++;                                  // exact count even if truncated
            }
        }
    }
    if (lane == 0) row[0] = (unsigned short)cnt;
}

// ---------------------------------------------------------------------------
// K2: lex-first-MIS greedy + integrated exact fallback. grid = BATCH*NC,
// 1024 thr. Rows in registers (2 nodes/thread); one barrier per round.
// ---------------------------------------------------------------------------
#define MS_KEY  0
#define MS_SBOX 0
#define MS_SAR  32768
#define MS_ST   40960
#define MS_CNT  43008
#define MS_SMEM 43040

__device__ __forceinline__ unsigned flipkey(float s) {
    unsigned u = __float_as_uint(s);
    return (u & 0x80000000u) ? ~u : (u | 0x80000000u);   // total order on floats
}

__global__ void __launch_bounds__(1024) mis_kernel(const float4* __restrict__ boxes,
                                                   const float* __restrict__ scores,
                                                   const float* __restrict__ thrp,
                                                   const float* __restrict__ sthrp,
                                                   float* __restrict__ out) {
    extern __shared__ unsigned char sm[];
    unsigned*               skey  = (unsigned*)(sm + MS_KEY);
    float4*                 fsbox = (float4*)(sm + MS_SBOX);
    float*                  fsar  = (float*)(sm + MS_SAR);
    volatile unsigned char* sst   = sm + MS_ST;
    volatile int*           scnt  = (int*)(sm + MS_CNT);

    int bc = blockIdx.x, b = bc >> 2;
    int tid = threadIdx.x, lane = tid & 31, warp = tid >> 5;
    float sthr = sthrp[0];
    bool selfm = thrp[0] < 1.0f;        // self-IoU = 1 claims self iff thr < 1
    const float* spc = scores + (size_t)bc * NB;
    float*       opc = out + (size_t)bc * NB;

    if (tid == 0) scnt[1] = 0;

    int n0 = tid, n1 = tid + 1024;
    ushort4 r0[4], r1[4];
    {
        const uint4* g0 = (const uint4*)(G_ADJ + (size_t)(b * NB + n0) * ROWSL);
        const uint4* g1 = (const uint4*)(G_ADJ + (size_t)(b * NB + n1) * ROWSL);
        uint4 a = g0[0], c = g1[0];
        r0[0] = *(ushort4*)&a.x; r0[1] = *(ushort4*)&a.z;
        uint4 a2 = g0[1], c2 = g1[1];
        r0[2] = *(ushort4*)&a2.x; r0[3] = *(ushort4*)&a2.z;
        r1[0] = *(ushort4*)&c.x; r1[1] = *(ushort4*)&c.z;
        r1[2] = *(ushort4*)&c2.x; r1[3] = *(ushort4*)&c2.z;
    }
    const unsigned short* e0 = (const unsigned short*)r0;
    const unsigned short* e1 = (const unsigned short*)r1;
    int d0 = e0[0], d1 = e1[0];
    if (d0 > MAXDEG || d1 > MAXDEG) scnt[1] = 1;

    float s0 = spc[n0], s1 = spc[n1];
    skey[n0] = flipkey(s0);
    skey[n1] = flipkey(s1);
    unsigned char st0, st1;
    if (s0 > sthr) { if (d0 == 0) { st0 = 3; opc[n0] = selfm ? (float)n0 : -1.0f; } else st0 = 0; }
    else           { st0 = 3; opc[n0] = -1.0f; }
    if (s1 > sthr) { if (d1 == 0) { st1 = 3; opc[n1] = selfm ? (float)n1 : -1.0f; } else st1 = 0; }
    else           { st1 = 3; opc[n1] = -1.0f; }
    sst[n0] = st0;
    sst[n1] = st1;
    __syncthreads();

    if (scnt[1] == 0) {
        bool u0 = (st0 == 0), u1 = (st1 == 0);
        for (int round = 0; round < 4096; round++) {
            if (u0) {
                unsigned mk = skey[n0];
                bool blocked = false, claimed = false;
                #pragma unroll
                for (int e = 1; e <= MAXDEG; e++) {
                    if (e > d0) break;
                    int u = e0[e];
                    unsigned char stu = sst[u];
                    if (stu >= 2) continue;
                    unsigned fu = skey[u];
                    bool hp = (fu > mk) || (fu == mk && u < n0);
                    if (!hp) continue;
                    if (stu == 1) { claimed = true; break; }
                    blocked = true;
                }
                if (claimed)       { sst[n0] = 2; u0 = false; }
                else if (!blocked) { sst[n0] = 1; u0 = false; }
            }
            if (u1) {
                unsigned mk = skey[n1];
                bool blocked = false, claimed = false;
                #pragma unroll
                for (int e = 1; e <= MAXDEG; e++) {
                    if (e > d1) break;
                    int u = e1[e];
                    unsigned char stu = sst[u];
                    if (stu >= 2) continue;
                    unsigned fu = skey[u];
                    bool hp = (fu > mk) || (fu == mk && u < n1);
                    if (!hp) continue;
                    if (stu == 1) { claimed = true; break; }
                    blocked = true;
                }
                if (claimed)       { sst[n1] = 2; u1 = false; }
                else if (!blocked) { sst[n1] = 1; u1 = false; }
            }
            if (u0 | u1) scnt[0] = round + 1;        // benign race: same value
            __syncthreads();
            if (scnt[0] != round + 1) break;
        }

        unsigned char f0 = sst[n0], f1 = sst[n1];
        if (f0 == 1) opc[n0] = (float)n0;
        else if (f0 == 2) {
            unsigned bk = 0; int bu = -1;
            #pragma unroll
            for (int e = 1; e <= MAXDEG; e++) {
                if (e > d0) break;
                int u = e0[e];
                if (sst[u] == 1) {
                    unsigned fu = skey[u];
                    if (bu < 0 || fu > bk || (fu == bk && u < bu)) { bk = fu; bu = u; }
                }
            }
            opc[n0] = (float)bu;
        }
        if (f1 == 1) opc[n1] = (float)n1;
        else if (f1 == 2) {
            unsigned bk = 0; int bu = -1;
            #pragma unroll
            for (int e = 1; e <= MAXDEG; e++) {
                if (e > d1) break;
                int u = e1[e];
                if (sst[u] == 1) {
                    unsigned fu = skey[u];
                    if (bu < 0 || fu > bk || (fu == bk && u < bu)) { bk = fu; bu = u; }
                }
            }
            opc[n1] = (float)bu;
        }
        return;
    }

    // ---- integrated exact fallback for THIS (b,c) (adversarial only) ----
    {
        float thr = thrp[0];
        const float4* bb = boxes + (size_t)b * NB;
        for (int i = tid; i < NB; i += 1024) {
            float4 v = bb[i];
            fsbox[i] = v;
            fsar[i] = (v.z - v.x) * (v.w - v.y);
        }
        for (int n = tid; n < NB; n += 1024) {
            sst[n] = (spc[n] > sthr) ? 0 : 1;
            opc[n] = -1.0f;
        }
        __syncthreads();

        if (warp == 0) {
            for (;;) {
                float bs = -1e30f; int bi = 1 << 30;
                for (int k = 0; k < NB / 32; k++) {
                    int u = k * 32 + lane;
                    if (!sst[u]) {
                        float s = spc[u];
                        if (s > bs || (s == bs && u < bi)) { bs = s; bi = u; }
                    }
                }
                #pragma unroll
                for (int off = 16; off; off >>= 1) {
                    float os = __shfl_down_sync(0xffffffffu, bs, off);
                    int   oi = __shfl_down_sync(0xffffffffu, bi, off);
                    if (os > bs || (os == bs && oi < bi)) { bs = os; bi = oi; }
                }
                bi = __shfl_sync(0xffffffffu, bi, 0);
                if (bi >= (1 << 30)) break;

                float4 tb = fsbox[bi];
                float tar = fsar[bi];
                float lf = (float)bi;
                for (int k = 0; k < NB / 32; k++) {
                    int u = k * 32 + lane;
                    if (!sst[u]) {
                        float4 ub = fsbox[u];
                        float ix = fminf(tb.z, ub.z) - fmaxf(tb.x, ub.x);
                        float iy = fminf(tb.w, ub.w) - fmaxf(tb.y, ub.y);
                        ix = fmaxf(ix, 0.0f);
                        iy = fmaxf(iy, 0.0f);
                        float inter = ix * iy;
                        float unim  = fmaxf(tar + fsar[u] - inter, 1e-6f);
                        if (inter > thr * unim) { sst[u] = 1; opc[u] = lf; }
                    }
                }
                if (lane == 0) sst[bi] = 1;
                __syncwarp();
            }
        }
    }
}

// ---------------------------------------------------------------------------
extern "C" void kernel_launch(void* const* d_in, const int* in_sizes, int n_in,
                              void* d_out, int out_size) {
    const float4* boxes  = (const float4*)d_in[0];
    const float*  scores = (const float*)d_in[1];
    const float*  iouthr = (const float*)d_in[2];
    const float*  scothr = (const float*)d_in[3];
    float* out = (float*)d_out;

    cudaFuncSetAttribute(mis_kernel, cudaFuncAttributeMaxDynamicSharedMemorySize, MS_SMEM);

    sort_kernel<<<BATCH, 1024>>>(boxes);
    adj_kernel<<<BATCH * 128, 512>>>(iouthr);
    mis_kernel<<<BATCH * NC, 1024, MS_SMEM>>>(boxes, scores, iouthr, scothr, out);
}

// round 15
// speedup vs baseline: 1.2396x; 1.0095x over previous
#include <cuda_runtime.h>
#include <cuda_bf16.h>

#define BATCH  4
#define NB     2048
#define NC     4
#define ROWSL  16          // u16 slots per row: [0]=count, [1..15]=neighbors
#define MAXDEG 15
#define NBINS  64
#define XSCALE 0.0625f     // fixed binning: bin = clamp((int)(x1/16), 0, 63)
#define BINW   16.0f
#define SGRID  32          // sort blocks (8 per batch) — all co-resident
#define STPB   256

// __device__ scratch (allocation-free rule). uint4 => 32B-aligned rows.
__device__ uint4 g_adj_raw[(size_t)BATCH * NB * ROWSL / 8];
#define G_ADJ ((unsigned short*)g_adj_raw)
__device__ float4         g_sbox[BATCH * NB];      // bin-sorted boxes (by x1)
__device__ unsigned short g_sidx[BATCH * NB];      // sorted pos -> original idx
__device__ int            g_binoff[BATCH][NBINS + 1];
__device__ float          g_wmax[BATCH];           // per-batch max box width
__device__ int            g_bhist[BATCH][8][NBINS];
__device__ float          g_bwmax[BATCH][8];

// Grid barrier (replay-safe: gen monotone, cnt returns to 0).
__device__ unsigned           g_barcnt = 0;
__device__ volatile unsigned  g_bargen = 0;

__device__ __forceinline__ void gridbar32() {
    __syncthreads();
    if (threadIdx.x == 0) {
        unsigned gen = g_bargen;
        __threadfence();
        unsigned t = atomicAdd(&g_barcnt, 1);
        if (t == SGRID - 1) {
            atomicExch(&g_barcnt, 0);
            __threadfence();
            g_bargen = gen + 1;
        } else {
            while (g_bargen == gen) { }
            __threadfence();
        }
    }
    __syncthreads();
}

// ---------------------------------------------------------------------------
// K0: distributed counting sort. grid = 32, block = 256, 1 box/thread.
// Phase 1: per-block hist (+rank from the same atomic) + partial wmax.
// gridbar. Phase 2: batch totals, warp-scan, cross-block base, scatter.
// ---------------------------------------------------------------------------
__global__ void __launch_bounds__(STPB) sort_kernel(const float4* __restrict__ boxes) {
    __shared__ int   shist[NBINS];
    __shared__ int   stot[NBINS], smyb[NBINS], sbase[NBINS];
    __shared__ int   sboff[NBINS + 1];
    __shared__ float swred[8];

    int blk = blockIdx.x;
    int b = blk >> 3, sub = blk & 7;
    int tid = threadIdx.x, lane = tid & 31, warp = tid >> 5;

    if (tid < NBINS) shist[tid] = 0;
    __syncthreads();

    int i = sub * STPB + tid;                       // box index in batch
    float4 v = boxes[(size_t)b * NB + i];
    int bin = min(NBINS - 1, max(0, (int)(v.x * XSCALE)));
    int rank = atomicAdd(&shist[bin], 1);           // rank within (block, bin)

    float w = v.z - v.x;
    #pragma unroll
    for (int o = 16; o; o >>= 1)
        w = fmaxf(w, __shfl_xor_sync(0xffffffffu, w, o));
    if (lane == 0) swred[warp] = w;
    __syncthreads();

    if (tid < NBINS) g_bhist[b][sub][tid] = shist[tid];
    if (tid == 0) {
        float m = swred[0];
        #pragma unroll
        for (int j = 1; j < 8; j++) m = fmaxf(m, swred[j]);
        g_bwmax[b][sub] = m;
    }

    gridbar32();                                    // fences publish g_bhist/g_bwmax

    // Phase 2: batch totals + this block's cross-block base per bin.
    if (tid < NBINS) {
        int acc = 0, myb = 0;
        #pragma unroll
        for (int s = 0; s < 8; s++) {
            int t = g_bhist[b][s][tid];
            if (s < sub) myb += t;
            acc += t;
        }
        stot[tid] = acc;
        smyb[tid] = myb;
    }
    __syncthreads();

    if (warp == 0) {                                // exclusive scan of 64 totals
        int a0 = stot[lane], a1 = stot[lane + 32];
        #pragma unroll
        for (int o = 1; o < 32; o <<= 1) {
            int n = __shfl_up_sync(0xffffffffu, a0, o);
            if (lane >= o) a0 += n;
        }
        int tot0 = __shfl_sync(0xffffffffu, a0, 31);
        #pragma unroll
        for (int o = 1; o < 32; o <<= 1) {
            int n = __shfl_up_sync(0xffffffffu, a1, o);
            if (lane >= o) a1 += n;
        }
        a1 += tot0;
        if (lane == 0) sboff[0] = 0;
        sboff[lane + 1] = a0;
        sboff[lane + 33] = a1;
    }
    __syncthreads();

    if (tid < NBINS) sbase[tid] = sboff[tid] + smyb[tid];
    __syncthreads();

    int pos = sbase[bin] + rank;
    g_sbox[(size_t)b * NB + pos] = v;
    g_sidx[(size_t)b * NB + pos] = (unsigned short)i;

    if (sub == 0) {
        if (tid <= NBINS) g_binoff[b][tid] = sboff[tid];
        if (tid == 0) {
            float m = g_bwmax[b][0];
            #pragma unroll
            for (int s = 1; s < 8; s++) m = fmaxf(m, g_bwmax[b][s]);
            g_wmax[b] = fmaxf(m, 0.0f);
        }
    }
}

// ---------------------------------------------------------------------------
// K1: adjacency rows over bin-sorted boxes. 512 blocks x 512 thr, 16 rows.
// Fixed binning; bin-safe break. Rows written at ORIGINAL indices.
// ---------------------------------------------------------------------------
__global__ void __launch_bounds__(512) adj_kernel(const float* __restrict__ thrp) {
    __shared__ float sx1[NB], sy1[NB], sx2[NB], sy2[NB], sar[NB];
    __shared__ unsigned short ssidx[NB];
    __shared__ int sboff[NBINS + 1];
    __shared__ float4 rowbox[16];
    __shared__ int s_lo, s_hi;

    int b    = blockIdx.x >> 7;
    int tile = blockIdx.x & 127;
    int tid  = threadIdx.x;
    int warp = tid >> 5, lane = tid & 31;

    float thr  = thrp[0];
    float wmax = g_wmax[b];
    bool windowed = (thr >= 0.0f);       // hit => x-overlap only valid for thr>=0

    if (tid <= NBINS) sboff[tid] = g_binoff[b][tid];
    if (tid < 16) rowbox[tid] = g_sbox[b * NB + tile * 16 + tid];
    __syncthreads();

    if (warp == 0) {
        float4 rv = rowbox[lane & 15];
        float r1 = rv.x, r2 = rv.z;
        #pragma unroll
        for (int o = 16; o; o >>= 1) {
            r1 = fminf(r1, __shfl_xor_sync(0xffffffffu, r1, o));
            r2 = fmaxf(r2, __shfl_xor_sync(0xffffffffu, r2, o));
        }
        if (lane == 0) {
            int lo = 0, hi = NB;
            if (windowed) {
                int bl = min(NBINS - 1, max(0, (int)((r1 - wmax) * XSCALE) - 1));
                int bh = min(NBINS, max(1, (int)(r2 * XSCALE) + 2));
                lo = sboff[bl] & ~31;
                hi = min(NB, (sboff[bh] + 31) & ~31);
            }
            s_lo = lo; s_hi = hi;
        }
    }
    __syncthreads();
    int lo = s_lo, hi = s_hi;

    const float4* sb = g_sbox + (size_t)b * NB;
    for (int i = lo + tid; i < hi; i += 512) {
        float4 v = sb[i];
        int k = i - lo;
        sx1[k] = v.x; sy1[k] = v.y; sx2[k] = v.z; sy2[k] = v.w;
        sar[k] = (v.z - v.x) * (v.w - v.y);
        ssidx[k] = g_sidx[b * NB + i];
    }
    __syncthreads();

    int p = tile * 16 + warp;            // sorted position of this row
    float4 rv = rowbox[warp];
    float rx1 = rv.x, ry1 = rv.y, rx2 = rv.z, ry2 = rv.w;
    float rar = (rx2 - rx1) * (ry2 - ry1);
    int orr = ssidx[p - lo];
    unsigned short* row = G_ADJ + (size_t)(b * NB + orr) * ROWSL;
    int cnt = 0;

    int c0 = lo >> 5;
    if (windowed) {
        int bl = min(NBINS - 1, max(0, (int)((rx1 - wmax) * XSCALE) - 1));
        c0 = max(c0, sboff[bl] >> 5);
    }

    for (int c = c0; c < (hi >> 5); c++) {
        if (windowed) {
            float x1c = sx1[c * 32 - lo];
            int bc = min(NBINS - 1, max(0, (int)(x1c * XSCALE)));
            if ((float)(bc - 1) * BINW > rx2) break;   // bin-safe lower bound
        }
        int k = c * 32 + lane - lo;
        float ix = fminf(rx2, sx2[k]) - fmaxf(rx1, sx1[k]);
        float iy = fminf(ry2, sy2[k]) - fmaxf(ry1, sy1[k]);
        ix = fmaxf(ix, 0.0f);
        iy = fmaxf(iy, 0.0f);
        float inter = ix * iy;
        float unim  = fmaxf(rar + sar[k] - inter, 1e-6f);
        bool hit = (inter > thr * unim) && (c * 32 + lane != p);   // drop self
        unsigned word = __ballot_sync(0xffffffffu, hit);
        if (lane == 0 && word) {
            int base = c * 32 - lo;
            while (word) {
                int j = __ffs(word) - 1;
                word &= word - 1u;
                if (cnt < MAXDEG) row[1 + cnt] = ssidx[base + j];
                cnt++;                                  // exact count even if truncated
            }
        }
    }
    if (lane == 0) row[0] = (unsigned short)cnt;
}

// ---------------------------------------------------------------------------
// K2: lex-first-MIS greedy + integrated exact fallback. grid = BATCH*NC,
// 1024 thr. Rows in registers (2 nodes/thread); one barrier per round.
// ---------------------------------------------------------------------------
#define MS_KEY  0
#define MS_SBOX 0
#define MS_SAR  32768
#define MS_ST   40960
#define MS_CNT  43008
#define MS_SMEM 43040

__device__ __forceinline__ unsigned flipkey(float s) {
    unsigned u = __float_as_uint(s);
    return (u & 0x80000000u) ? ~u : (u | 0x80000000u);   // total order on floats
}

__global__ void __launch_bounds__(1024) mis_kernel(const float4* __restrict__ boxes,
                                                   const float* __restrict__ scores,
                                                   const float* __restrict__ thrp,
                                                   const float* __restrict__ sthrp,
                                                   float* __restrict__ out) {
    extern __shared__ unsigned char sm[];
    unsigned*               skey  = (unsigned*)(sm + MS_KEY);
    float4*                 fsbox = (float4*)(sm + MS_SBOX);
    float*                  fsar  = (float*)(sm + MS_SAR);
    volatile unsigned char* sst   = sm + MS_ST;
    volatile int*           scnt  = (int*)(sm + MS_CNT);

    int bc = blockIdx.x, b = bc >> 2;
    int tid = threadIdx.x, lane = tid & 31, warp = tid >> 5;
    float sthr = sthrp[0];
    bool selfm = thrp[0] < 1.0f;        // self-IoU = 1 claims self iff thr < 1
    const float* spc = scores + (size_t)bc * NB;
    float*       opc = out + (size_t)bc * NB;

    if (tid == 0) scnt[1] = 0;

    int n0 = tid, n1 = tid + 1024;
    ushort4 r0[4], r1[4];
    {
        const uint4* g0 = (const uint4*)(G_ADJ + (size_t)(b * NB + n0) * ROWSL);
        const uint4* g1 = (const uint4*)(G_ADJ + (size_t)(b * NB + n1) * ROWSL);
        uint4 a = g0[0], c = g1[0];
        r0[0] = *(ushort4*)&a.x; r0[1] = *(ushort4*)&a.z;
        uint4 a2 = g0[1], c2 = g1[1];
        r0[2] = *(ushort4*)&a2.x; r0[3] = *(ushort4*)&a2.z;
        r1[0] = *(ushort4*)&c.x; r1[1] = *(ushort4*)&c.z;
        r1[2] = *(ushort4*)&c2.x; r1[3] = *(ushort4*)&c2.z;
    }
    const unsigned short* e0 = (const unsigned short*)r0;
    const unsigned short* e1 = (const unsigned short*)r1;
    int d0 = e0[0], d1 = e1[0];
    if (d0 > MAXDEG || d1 > MAXDEG) scnt[1] = 1;

    float s0 = spc[n0], s1 = spc[n1];
    skey[n0] = flipkey(s0);
    skey[n1] = flipkey(s1);
    unsigned char st0, st1;
    if (s0 > sthr) { if (d0 == 0) { st0 = 3; opc[n0] = selfm ? (float)n0 : -1.0f; } else st0 = 0; }
    else           { st0 = 3; opc[n0] = -1.0f; }
    if (s1 > sthr) { if (d1 == 0) { st1 = 3; opc[n1] = selfm ? (float)n1 : -1.0f; } else st1 = 0; }
    else           { st1 = 3; opc[n1] = -1.0f; }
    sst[n0] = st0;
    sst[n1] = st1;
    __syncthreads();

    if (scnt[1] == 0) {
        bool u0 = (st0 == 0), u1 = (st1 == 0);
        for (int round = 0; round < 4096; round++) {
            if (u0) {
                unsigned mk = skey[n0];
                bool blocked = false, claimed = false;
                #pragma unroll
                for (int e = 1; e <= MAXDEG; e++) {
                    if (e > d0) break;
                    int u = e0[e];
                    unsigned char stu = sst[u];
                    if (stu >= 2) continue;
                    unsigned fu = skey[u];
                    bool hp = (fu > mk) || (fu == mk && u < n0);
                    if (!hp) continue;
                    if (stu == 1) { claimed = true; break; }
                    blocked = true;
                }
                if (claimed)       { sst[n0] = 2; u0 = false; }
                else if (!blocked) { sst[n0] = 1; u0 = false; }
            }
            if (u1) {
                unsigned mk = skey[n1];
                bool blocked = false, claimed = false;
                #pragma unroll
                for (int e = 1; e <= MAXDEG; e++) {
                    if (e > d1) break;
                    int u = e1[e];
                    unsigned char stu = sst[u];
                    if (stu >= 2) continue;
                    unsigned fu = skey[u];
                    bool hp = (fu > mk) || (fu == mk && u < n1);
                    if (!hp) continue;
                    if (stu == 1) { claimed = true; break; }
                    blocked = true;
                }
                if (claimed)       { sst[n1] = 2; u1 = false; }
                else if (!blocked) { sst[n1] = 1; u1 = false; }
            }
            if (u0 | u1) scnt[0] = round + 1;        // benign race: same value
            __syncthreads();
            if (scnt[0] != round + 1) break;
        }

        unsigned char f0 = sst[n0], f1 = sst[n1];
        if (f0 == 1) opc[n0] = (float)n0;
        else if (f0 == 2) {
            unsigned bk = 0; int bu = -1;
            #pragma unroll
            for (int e = 1; e <= MAXDEG; e++) {
                if (e > d0) break;
                int u = e0[e];
                if (sst[u] == 1) {
                    unsigned fu = skey[u];
                    if (bu < 0 || fu > bk || (fu == bk && u < bu)) { bk = fu; bu = u; }
                }
            }
            opc[n0] = (float)bu;
        }
        if (f1 == 1) opc[n1] = (float)n1;
        else if (f1 == 2) {
            unsigned bk = 0; int bu = -1;
            #pragma unroll
            for (int e = 1; e <= MAXDEG; e++) {
                if (e > d1) break;
                int u = e1[e];
                if (sst[u] == 1) {
                    unsigned fu = skey[u];
                    if (bu < 0 || fu > bk || (fu == bk && u < bu)) { bk = fu; bu = u; }
                }
            }
            opc[n1] = (float)bu;
        }
        return;
    }

    // ---- integrated exact fallback for THIS (b,c) (adversarial only) ----
    {
        float thr = thrp[0];
        const float4* bb = boxes + (size_t)b * NB;
        for (int i = tid; i < NB; i += 1024) {
            float4 v = bb[i];
            fsbox[i] = v;
            fsar[i] = (v.z - v.x) * (v.w - v.y);
        }
        for (int n = tid; n < NB; n += 1024) {
            sst[n] = (spc[n] > sthr) ? 0 : 1;
            opc[n] = -1.0f;
        }
        __syncthreads();

        if (warp == 0) {
            for (;;) {
                float bs = -1e30f; int bi = 1 << 30;
                for (int k = 0; k < NB / 32; k++) {
                    int u = k * 32 + lane;
                    if (!sst[u]) {
                        float s = spc[u];
                        if (s > bs || (s == bs && u < bi)) { bs = s; bi = u; }
                    }
                }
                #pragma unroll
                for (int off = 16; off; off >>= 1) {
                    float os = __shfl_down_sync(0xffffffffu, bs, off);
                    int   oi = __shfl_down_sync(0xffffffffu, bi, off);
                    if (os > bs || (os == bs && oi < bi)) { bs = os; bi = oi; }
                }
                bi = __shfl_sync(0xffffffffu, bi, 0);
                if (bi >= (1 << 30)) break;

                float4 tb = fsbox[bi];
                float tar = fsar[bi];
                float lf = (float)bi;
                for (int k = 0; k < NB / 32; k++) {
                    int u = k * 32 + lane;
                    if (!sst[u]) {
                        float4 ub = fsbox[u];
                        float ix = fminf(tb.z, ub.z) - fmaxf(tb.x, ub.x);
                        float iy = fminf(tb.w, ub.w) - fmaxf(tb.y, ub.y);
                        ix = fmaxf(ix, 0.0f);
                        iy = fmaxf(iy, 0.0f);
                        float inter = ix * iy;
                        float unim  = fmaxf(tar + fsar[u] - inter, 1e-6f);
                        if (inter > thr * unim) { sst[u] = 1; opc[u] = lf; }
                    }
                }
                if (lane == 0) sst[bi] = 1;
                __syncwarp();
            }
        }
    }
}

// ---------------------------------------------------------------------------
extern "C" void kernel_launch(void* const* d_in, const int* in_sizes, int n_in,
                              void* d_out, int out_size) {
    const float4* boxes  = (const float4*)d_in[0];
    const float*  scores = (const float*)d_in[1];
    const float*  iouthr = (const float*)d_in[2];
    const float*  scothr = (const float*)d_in[3];
    float* out = (float*)d_out;

    cudaFuncSetAttribute(mis_kernel, cudaFuncAttributeMaxDynamicSharedMemorySize, MS_SMEM);

    sort_kernel<<<SGRID, STPB>>>(boxes);
    adj_kernel<<<BATCH * 128, 512>>>(iouthr);
    mis_kernel<<<BATCH * NC, 1024, MS_SMEM>>>(boxes, scores, iouthr, scothr, out);
}